// round 1
// baseline (speedup 1.0000x reference)
#include <cuda_runtime.h>

#define B_ 256
#define T_ 512
#define D_ 128
#define H_ 128
#define G_ 384          // 3H, gate order z|r|h
#define BT_ (B_*T_)

// Scratch (device globals: allocation-free rule). One xp buffer reused by both
// layers (layer0's xp is fully consumed before layer1's projection overwrites it).
__device__ float g_xp[(size_t)BT_ * G_];   // 201 MB
__device__ float g_h0[(size_t)BT_ * H_];   // 67 MB

typedef unsigned long long u64;

static __device__ __forceinline__ u64 pack2(float a, float b) {
    u64 r; asm("mov.b64 %0, {%1, %2};" : "=l"(r) : "f"(a), "f"(b)); return r;
}
static __device__ __forceinline__ void unpack2(u64 v, float &a, float &b) {
    asm("mov.b64 {%0, %1}, %2;" : "=f"(a), "=f"(b) : "l"(v));
}
// Packed fp32x2 FMA (Blackwell f32x2 pipe; 2 MACs/lane/instr)
static __device__ __forceinline__ u64 fma2(u64 a, u64 b, u64 c) {
    u64 d; asm("fma.rn.f32x2 %0, %1, %2, %3;" : "=l"(d) : "l"(a), "l"(b), "l"(c)); return d;
}

// ---------------------------------------------------------------------------
// Projection: out[n, g] = sum_k x[n,k] * W[k,g] + bias[g]
// 768 threads = 384 cols x 2 k-halves. W held in registers (32 x f32x2 pairs
// packed along k). Rows streamed 2 at a time through double-buffered smem.
// ---------------------------------------------------------------------------
#define PR_ 2
__global__ __launch_bounds__(768, 1)
void proj_kernel(const float* __restrict__ x, const float* __restrict__ W,
                 const float* __restrict__ bias, float* __restrict__ out,
                 int rows_per_block)
{
    __shared__ __align__(16) float x_sm[2][PR_][D_];
    __shared__ float part[PR_][2][G_];
    __shared__ float b_sm[G_];
    const int tid  = threadIdx.x;
    const int half = (tid >= G_) ? 1 : 0;
    const int col  = tid - half * G_;
    const int kb   = half * 64;

    u64 w2[32];
#pragma unroll
    for (int i = 0; i < 32; i++)
        w2[i] = pack2(W[(kb + 2*i) * G_ + col], W[(kb + 2*i + 1) * G_ + col]);
    if (tid < G_) b_sm[tid] = bias[tid];

    const int row0 = blockIdx.x * rows_per_block;
    if (tid < PR_ * D_) {
        int r = tid >> 7, k = tid & 127;
        x_sm[0][r][k] = x[(row0 + r) * D_ + k];
    }
    __syncthreads();

    const int iters = rows_per_block / PR_;
    int buf = 0;
    for (int it = 0; it < iters; it++) {
        const int rbase = row0 + it * PR_;
        // prefetch next row pair into the other buffer
        if (it + 1 < iters && tid < PR_ * D_) {
            int r = tid >> 7, k = tid & 127;
            x_sm[buf ^ 1][r][k] = x[(rbase + PR_ + r) * D_ + k];
        }
        u64 acc0 = 0ull, acc1 = 0ull;
#pragma unroll
        for (int i = 0; i < 16; i++) {
            ulonglong2 a = *(const ulonglong2*)&x_sm[buf][0][kb + 4*i];
            ulonglong2 b = *(const ulonglong2*)&x_sm[buf][1][kb + 4*i];
            acc0 = fma2(a.x, w2[2*i],     acc0);
            acc0 = fma2(a.y, w2[2*i + 1], acc0);
            acc1 = fma2(b.x, w2[2*i],     acc1);
            acc1 = fma2(b.y, w2[2*i + 1], acc1);
        }
        float p0a, p0b, p1a, p1b;
        unpack2(acc0, p0a, p0b); unpack2(acc1, p1a, p1b);
        part[0][half][col] = p0a + p0b;
        part[1][half][col] = p1a + p1b;
        __syncthreads();
        // 768 outputs = 768 threads: row = half, column = col
        out[(rbase + half) * G_ + col] =
            part[half][0][col] + part[half][1][col] + b_sm[col];
        __syncthreads();
        buf ^= 1;
    }
}

// ---------------------------------------------------------------------------
// GRU scan: one block owns 2 batch rows for all T steps (rows are independent).
// U register-resident (as in proj). h (2x128 floats) lives in smem, broadcast
// 64-bit/128-bit reads feed packed f32x2 FMAs. Gate math (sigmoid/tanh) done by
// 256 threads; xp for step t+1 prefetched from gmem during the FMA loop.
// ---------------------------------------------------------------------------
__global__ __launch_bounds__(768, 1)
void gru_scan(const float* __restrict__ U, const float* __restrict__ brec,
              const float* __restrict__ xp, float* __restrict__ out)
{
    __shared__ __align__(16) float h_sm[2][H_];
    __shared__ float part[2][2][G_];      // [row][k-half][col]
    __shared__ float xp_sm[2][2][G_];     // [buf][row][col]
    __shared__ float br_sm[G_];
    const int tid  = threadIdx.x;
    const int half = (tid >= G_) ? 1 : 0;
    const int col  = tid - half * G_;
    const int kb   = half * 64;

    u64 u2[32];
#pragma unroll
    for (int i = 0; i < 32; i++)
        u2[i] = pack2(U[(kb + 2*i) * G_ + col], U[(kb + 2*i + 1) * G_ + col]);
    if (tid < G_) br_sm[tid] = brec[tid];
    if (tid < 2 * H_) h_sm[tid >> 7][tid & 127] = 0.0f;

    const int b0 = blockIdx.x * 2;
    const float* xr0 = xp + (size_t)b0 * T_ * G_;
    const float* xr1 = xp + (size_t)(b0 + 1) * T_ * G_;
    float* o0 = out + (size_t)b0 * T_ * H_;
    float* o1 = out + (size_t)(b0 + 1) * T_ * H_;

    // preload xp for t=0 into buffer 0
    xp_sm[0][half][col] = (half ? xr1 : xr0)[col];
    __syncthreads();

    for (int t = 0; t < T_; t++) {
        const int buf = t & 1;
        float xpre = 0.0f;
        if (t + 1 < T_) xpre = (half ? xr1 : xr0)[(t + 1) * G_ + col];

        u64 acc0 = 0ull, acc1 = 0ull;
#pragma unroll
        for (int i = 0; i < 16; i++) {
            ulonglong2 a = *(const ulonglong2*)&h_sm[0][kb + 4*i];  // broadcast
            ulonglong2 b = *(const ulonglong2*)&h_sm[1][kb + 4*i];
            acc0 = fma2(a.x, u2[2*i],     acc0);
            acc0 = fma2(a.y, u2[2*i + 1], acc0);
            acc1 = fma2(b.x, u2[2*i],     acc1);
            acc1 = fma2(b.y, u2[2*i + 1], acc1);
        }
        float s0a, s0b, s1a, s1b;
        unpack2(acc0, s0a, s0b); unpack2(acc1, s1a, s1b);
        part[0][half][col] = s0a + s0b;
        part[1][half][col] = s1a + s1b;
        if (t + 1 < T_) xp_sm[buf ^ 1][half][col] = xpre;
        __syncthreads();

        if (tid < 2 * H_) {
            const int row = tid >> 7, u = tid & 127;
            float rz = part[row][0][u]        + part[row][1][u]        + br_sm[u];
            float rr = part[row][0][u + H_]   + part[row][1][u + H_]   + br_sm[u + H_];
            float rh = part[row][0][u + 2*H_] + part[row][1][u + 2*H_] + br_sm[u + 2*H_];
            float xz = xp_sm[buf][row][u];
            float xr = xp_sm[buf][row][u + H_];
            float xh = xp_sm[buf][row][u + 2*H_];
            float z  = 1.0f / (1.0f + __expf(-(xz + rz)));
            float r  = 1.0f / (1.0f + __expf(-(xr + rr)));
            float hh = tanhf(xh + r * rh);
            float hp = h_sm[row][u];
            float hn = z * hp + (1.0f - z) * hh;
            h_sm[row][u] = hn;
            (row ? o1 : o0)[t * H_ + u] = hn;
        }
        __syncthreads();
    }
}

// ---------------------------------------------------------------------------
extern "C" void kernel_launch(void* const* d_in, const int* in_sizes, int n_in,
                              void* d_out, int out_size)
{
    const float* x  = (const float*)d_in[0];
    const float* W0 = (const float*)d_in[1];
    const float* U0 = (const float*)d_in[2];
    const float* b0 = (const float*)d_in[3];
    const float* W1 = (const float*)d_in[4];
    const float* U1 = (const float*)d_in[5];
    const float* b1 = (const float*)d_in[6];
    float* out = (float*)d_out;

    float *xp, *h0;
    cudaGetSymbolAddress((void**)&xp, g_xp);
    cudaGetSymbolAddress((void**)&h0, g_h0);

    const int PROJ_GRID = 512;
    const int rpb = BT_ / PROJ_GRID;   // 256 rows per block

    // layer 0
    proj_kernel<<<PROJ_GRID, 768>>>(x, W0, b0 /*b_in*/, xp, rpb);
    gru_scan<<<B_ / 2, 768>>>(U0, b0 + G_ /*b_rec*/, xp, h0);
    // layer 1
    proj_kernel<<<PROJ_GRID, 768>>>(h0, W1, b1, xp, rpb);
    gru_scan<<<B_ / 2, 768>>>(U1, b1 + G_, xp, out);
}

// round 2
// speedup vs baseline: 1.7520x; 1.7520x over previous
#include <cuda_runtime.h>

#define B_ 256
#define T_ 512
#define D_ 128
#define H_ 128
#define G_ 384          // 3H, gate order z|r|h
#define BT_ (B_*T_)

__device__ float g_xp[(size_t)BT_ * G_];   // 201 MB scratch
__device__ float g_h0[(size_t)BT_ * H_];   // 67 MB scratch

typedef unsigned long long u64;

static __device__ __forceinline__ u64 pack2(float a, float b) {
    u64 r; asm("mov.b64 %0, {%1, %2};" : "=l"(r) : "f"(a), "f"(b)); return r;
}
static __device__ __forceinline__ void unpack2(u64 v, float &a, float &b) {
    asm("mov.b64 {%0, %1}, %2;" : "=f"(a), "=f"(b) : "l"(v));
}
// Packed fp32x2 FMA (Blackwell FFMA2; 2 MACs/lane/instr)
static __device__ __forceinline__ u64 fma2(u64 a, u64 b, u64 c) {
    u64 d; asm("fma.rn.f32x2 %0, %1, %2, %3;" : "=l"(d) : "l"(a), "l"(b), "l"(c)); return d;
}

// ---------------------------------------------------------------------------
// Layout shared by both kernels: 384 threads = 4 k-groups (32 k each) x 96
// j-groups (4 cols each). Each thread holds W/U[32k x 4j] in regs as 64 f32x2
// pairs packed along k. Per row: 8 broadcast LDS.128 feed 64 FFMA2
// -> crossbar cycles == FMA cycles (balanced), vs 4:1 LDS-bound before.
// ---------------------------------------------------------------------------

// Projection: out[n,g] = sum_k x[n,k]*W[k,g] + bias[g]. 2 rows per iter,
// double-buffered x in smem, 4-way k-split reduced via smem partials.
__global__ __launch_bounds__(384, 1)
void proj_kernel(const float* __restrict__ x, const float* __restrict__ W,
                 const float* __restrict__ bias, float* __restrict__ out,
                 int rows_per_block)
{
    __shared__ __align__(16) float x_sm[2][2][D_];
    __shared__ __align__(16) float part[2][4][G_];   // [row][kg][j]
    __shared__ float b_sm[G_];
    const int tid = threadIdx.x;
    const int kg  = tid / 96;          // 0..3  (warp-uniform: 96 = 3 warps)
    const int jg  = tid - kg * 96;     // 0..95
    const int j0  = jg * 4;
    const int kb  = kg * 32;

    u64 w2[16][4];
#pragma unroll
    for (int i = 0; i < 16; i++)
#pragma unroll
        for (int jj = 0; jj < 4; jj++)
            w2[i][jj] = pack2(W[(kb + 2*i) * G_ + j0 + jj],
                              W[(kb + 2*i + 1) * G_ + j0 + jj]);
    b_sm[tid] = bias[tid];

    const int row0 = blockIdx.x * rows_per_block;
    if (tid < 256) {
        int r = tid >> 7, k = tid & 127;
        x_sm[0][r][k] = x[(row0 + r) * D_ + k];
    }
    __syncthreads();

    const int iters = rows_per_block / 2;
    int buf = 0;
    for (int it = 0; it < iters; it++) {
        const int rbase = row0 + it * 2;
        if (it + 1 < iters && tid < 256) {
            int r = tid >> 7, k = tid & 127;
            x_sm[buf ^ 1][r][k] = x[(rbase + 2 + r) * D_ + k];
        }
        u64 acc[2][4] = {};
#pragma unroll
        for (int r = 0; r < 2; r++) {
#pragma unroll
            for (int i2 = 0; i2 < 8; i2++) {
                ulonglong2 hv = *(const ulonglong2*)&x_sm[buf][r][kb + 4*i2];
#pragma unroll
                for (int jj = 0; jj < 4; jj++) {
                    acc[r][jj] = fma2(hv.x, w2[2*i2][jj],     acc[r][jj]);
                    acc[r][jj] = fma2(hv.y, w2[2*i2 + 1][jj], acc[r][jj]);
                }
            }
        }
#pragma unroll
        for (int r = 0; r < 2; r++) {
            float4 p;
            float a, b;
            unpack2(acc[r][0], a, b); p.x = a + b;
            unpack2(acc[r][1], a, b); p.y = a + b;
            unpack2(acc[r][2], a, b); p.z = a + b;
            unpack2(acc[r][3], a, b); p.w = a + b;
            *(float4*)&part[r][kg][j0] = p;
        }
        __syncthreads();
        // 768 outputs by 384 threads: each does (r=0,1, j=tid)
#pragma unroll
        for (int r = 0; r < 2; r++) {
            float s = part[r][0][tid] + part[r][1][tid]
                    + part[r][2][tid] + part[r][3][tid] + b_sm[tid];
            out[(size_t)(rbase + r) * G_ + tid] = s;
        }
        __syncthreads();
        buf ^= 1;
    }
}

// ---------------------------------------------------------------------------
// GRU scan: one block owns 2 batch rows for all T steps. U register-resident
// in the 4kg x 96jg x 4j layout. 2 barriers/step: (A) matvec + partial store +
// xp prefetch, (B) 256-thread gate epilogue reducing partials directly.
// ---------------------------------------------------------------------------
__global__ __launch_bounds__(384, 1)
void gru_scan(const float* __restrict__ U, const float* __restrict__ brec,
              const float* __restrict__ xp, float* __restrict__ out)
{
    __shared__ __align__(16) float h_sm[2][H_];
    __shared__ __align__(16) float part[2][4][G_];   // [row][kg][j]
    __shared__ float xp_sm[2][2][G_];                // [buf][row][j]
    __shared__ float br_sm[G_];
    const int tid = threadIdx.x;
    const int kg  = tid / 96;
    const int jg  = tid - kg * 96;
    const int j0  = jg * 4;
    const int kb  = kg * 32;

    u64 u2[16][4];
#pragma unroll
    for (int i = 0; i < 16; i++)
#pragma unroll
        for (int jj = 0; jj < 4; jj++)
            u2[i][jj] = pack2(U[(kb + 2*i) * G_ + j0 + jj],
                              U[(kb + 2*i + 1) * G_ + j0 + jj]);
    br_sm[tid] = brec[tid];
    if (tid < 2 * H_) h_sm[tid >> 7][tid & 127] = 0.0f;

    const int b0 = blockIdx.x * 2;
    const float* xr0 = xp + (size_t)b0 * T_ * G_;
    const float* xr1 = xp + (size_t)(b0 + 1) * T_ * G_;
    float* o0 = out + (size_t)b0 * T_ * H_;
    float* o1 = out + (size_t)(b0 + 1) * T_ * H_;

    // preload xp for t=0 into buffer 0
    xp_sm[0][0][tid] = xr0[tid];
    xp_sm[0][1][tid] = xr1[tid];
    __syncthreads();

    for (int t = 0; t < T_; t++) {
        const int buf = t & 1;
        float xpre0 = 0.0f, xpre1 = 0.0f;
        if (t + 1 < T_) {
            xpre0 = xr0[(size_t)(t + 1) * G_ + tid];
            xpre1 = xr1[(size_t)(t + 1) * G_ + tid];
        }

        u64 acc[2][4] = {};
#pragma unroll
        for (int r = 0; r < 2; r++) {
#pragma unroll
            for (int i2 = 0; i2 < 8; i2++) {
                ulonglong2 hv = *(const ulonglong2*)&h_sm[r][kb + 4*i2];
#pragma unroll
                for (int jj = 0; jj < 4; jj++) {
                    acc[r][jj] = fma2(hv.x, u2[2*i2][jj],     acc[r][jj]);
                    acc[r][jj] = fma2(hv.y, u2[2*i2 + 1][jj], acc[r][jj]);
                }
            }
        }
#pragma unroll
        for (int r = 0; r < 2; r++) {
            float4 p;
            float a, b;
            unpack2(acc[r][0], a, b); p.x = a + b;
            unpack2(acc[r][1], a, b); p.y = a + b;
            unpack2(acc[r][2], a, b); p.z = a + b;
            unpack2(acc[r][3], a, b); p.w = a + b;
            *(float4*)&part[r][kg][j0] = p;
        }
        if (t + 1 < T_) {
            xp_sm[buf ^ 1][0][tid] = xpre0;
            xp_sm[buf ^ 1][1][tid] = xpre1;
        }
        __syncthreads();

        if (tid < 2 * H_) {
            const int row = tid >> 7, u = tid & 127;
            float rz = part[row][0][u] + part[row][1][u]
                     + part[row][2][u] + part[row][3][u] + br_sm[u];
            float rr = part[row][0][u+H_] + part[row][1][u+H_]
                     + part[row][2][u+H_] + part[row][3][u+H_] + br_sm[u+H_];
            float rh = part[row][0][u+2*H_] + part[row][1][u+2*H_]
                     + part[row][2][u+2*H_] + part[row][3][u+2*H_] + br_sm[u+2*H_];
            float xz = xp_sm[buf][row][u];
            float xr = xp_sm[buf][row][u + H_];
            float xh = xp_sm[buf][row][u + 2*H_];
            float z  = 1.0f / (1.0f + __expf(-(xz + rz)));
            float r  = 1.0f / (1.0f + __expf(-(xr + rr)));
            float hh = tanhf(xh + r * rh);
            float hp = h_sm[row][u];
            float hn = z * hp + (1.0f - z) * hh;
            h_sm[row][u] = hn;
            (row ? o1 : o0)[(size_t)t * H_ + u] = hn;
        }
        __syncthreads();
    }
}

// ---------------------------------------------------------------------------
extern "C" void kernel_launch(void* const* d_in, const int* in_sizes, int n_in,
                              void* d_out, int out_size)
{
    const float* x  = (const float*)d_in[0];
    const float* W0 = (const float*)d_in[1];
    const float* U0 = (const float*)d_in[2];
    const float* b0 = (const float*)d_in[3];
    const float* W1 = (const float*)d_in[4];
    const float* U1 = (const float*)d_in[5];
    const float* b1 = (const float*)d_in[6];
    float* out = (float*)d_out;

    float *xp, *h0;
    cudaGetSymbolAddress((void**)&xp, g_xp);
    cudaGetSymbolAddress((void**)&h0, g_h0);

    const int PROJ_GRID = 1024;
    const int rpb = BT_ / PROJ_GRID;   // 128 rows per block

    // layer 0
    proj_kernel<<<PROJ_GRID, 384>>>(x, W0, b0 /*b_in*/, xp, rpb);
    gru_scan<<<B_ / 2, 384>>>(U0, b0 + G_ /*b_rec*/, xp, h0);
    // layer 1
    proj_kernel<<<PROJ_GRID, 384>>>(h0, W1, b1, xp, rpb);
    gru_scan<<<B_ / 2, 384>>>(U1, b1 + G_, xp, out);
}